// round 14
// baseline (speedup 1.0000x reference)
#include <cuda_runtime.h>
#include <math.h>

typedef unsigned long long u64;

#define PI2_128 0.04908738521234052f   // 2*pi/128

__device__ __forceinline__ u64 pk2(float lo, float hi) {
    u64 r; asm("mov.b64 %0,{%1,%2};" : "=l"(r) : "f"(lo), "f"(hi)); return r;
}
__device__ __forceinline__ void upk2(u64 a, float& lo, float& hi) {
    asm("mov.b64 {%0,%1},%2;" : "=f"(lo), "=f"(hi) : "l"(a));
}
__device__ __forceinline__ u64 f2fma(u64 a, u64 b, u64 c) {
    u64 d; asm("fma.rn.f32x2 %0,%1,%2,%3;" : "=l"(d) : "l"(a), "l"(b), "l"(c)); return d;
}
__device__ __forceinline__ u64 f2add(u64 a, u64 b) {
    u64 d; asm("add.rn.f32x2 %0,%1,%2;" : "=l"(d) : "l"(a), "l"(b)); return d;
}
__device__ __forceinline__ u64 f2sub(u64 a, u64 b) {
    u64 d; asm("sub.rn.f32x2 %0,%1,%2;" : "=l"(d) : "l"(a), "l"(b)); return d;
}
__device__ __forceinline__ float shrinkf(float v) {
    float a = fabsf(v) - 0.01f;
    return a > 0.f ? copysignf(a, v) : 0.f;
}

// Scratch in [bc][450] contiguous layout: element = (re,im) packed u64.
__device__ u64 g_X[6144 * 450];
__device__ u64 g_F[6144 * 450];

// ===========================================================================
// Kernel 1: forward pruned DFT, double-folded in x, folded in y.
// One CTA per (b,c).  smem 56,576 B -> 4 CTAs/SM.
//
// smem (u64 units, total 7072):
//   EOe [0..2112)     64 y * 33 x (chunk-local)   (Xs[450] overlays later)
//   EOo [2112..4224)
//   tw  [4224..4768)  34 x-slots * 16 w-slots, (cos, -sin) (x 0..32 filled)
//   G2  [4768..6816)  128 y * 16 slots
//   cs4 [6816..7072)  128 * ulonglong2 ((c,c),(s,s))
// ===========================================================================
#define K1_SMEM 56576

__global__ __launch_bounds__(256, 4) void k_fwd(const float* __restrict__ x,
                                                const float* __restrict__ alpha)
{
    extern __shared__ u64 smu[];
    u64* EOe = smu;                      // [yl*33 + x], yl 0..63
    u64* EOo = smu + 2112;
    u64* Xs  = smu;                      // overlays EO after stage 1
    u64* tw  = smu + 4224;               // [x*16 + slot]
    u64* G2  = smu + 4768;               // [y*16 + slot]
    ulonglong2* cs4 = (ulonglong2*)(smu + 6816);

    const int t  = threadIdx.x;
    const int bc = blockIdx.x;
    const int b  = bc / 768, c = bc - b * 768;

    // ---- base trig table ----
    if (t < 128) {
        float cv, sv;
        sincosf(t * PI2_128, &sv, &cv);
        ulonglong2 e; e.x = pk2(cv, cv); e.y = pk2(sv, sv);
        cs4[t] = e;
    }
    __syncthreads();

    // ---- tw table: (cos(wx), -sin(wx)); slots 0..7 = even w {2..16},
    //      slots 8..14 = odd w {3..15}, slot 15 zero ----
    for (int i = t; i < 33 * 16; i += 256) {
        int xx = i >> 4, s = i & 15;
        if (s < 15) {
            int w = (s < 8) ? (2 * s + 2) : (2 * s - 13);
            ulonglong2 e = cs4[(w * xx) & 127];
            float cv, dum, sv;
            upk2(e.x, cv, dum);
            upk2(e.y, sv, dum);
            tw[i] = pk2(cv, -sv);
        } else {
            tw[i] = 0ull;
        }
    }

    // ---- 2 chunks of 64 rows: load + double x-fold -> EO, W-DFT -> G2 ----
    const int wrp = t >> 5, l = t & 31;
    const float* src = x + (size_t)bc * 16384;
    for (int ck = 0; ck < 2; ck++) {
        const int y0 = ck * 64;
        if (ck > 0) __syncthreads();     // EO reuse barrier
        // load + fold (x double symmetry) via warp shuffles
        for (int i = 0; i < 8; i++) {
            int yl = wrp * 8 + i;
            const float* row = src + (y0 + yl) * 128;
            float a = row[l];            // v[l]        l=0..31
            float u = row[32 + l];       // v[32+l]
            float m = row[64 + l];       // v[64+l]
            float q = row[96 + l];       // v[96+l]
            float Bu = __shfl_sync(0xffffffffu, u, (32 - l) & 31); // v[64-l]
            float Dq = __shfl_sync(0xffffffffu, q, (32 - l) & 31); // v[128-l]
            float v32 = __shfl_sync(0xffffffffu, u, 0);
            float v96 = __shfl_sync(0xffffffffu, q, 0);
            float Ep, Em, Om, Op;
            if (l == 0) {
                Ep = a + m;  Em = a - m;  Om = 0.f;  Op = 0.f;
            } else {
                float AD = a + Dq, ADm = a - Dq;
                float BC = Bu + m, CBm = m - Bu;
                Ep = AD + BC;  Em = AD - BC;
                Om = ADm + CBm; Op = ADm - CBm;
            }
            EOe[yl * 33 + l] = pk2(Ep, Om);
            EOo[yl * 33 + l] = pk2(Em, Op);
            if (l == 0) {                // x=32 self-paired point
                u64 e32 = pk2(v32 + v96, v32 - v96);
                EOe[yl * 33 + 32] = e32;
                EOo[yl * 33 + 32] = e32; // tw trig kills wrong halves
            }
        }
        __syncthreads();

        // stage 1: thread = (2 rows, 2 slots); x loop 0..31 + x=32 tail
        {
            const int wq = t & 7;
            const int yg = t >> 3;        // rows yg, yg+32 within chunk
            const int s0 = wq * 2;
            const u64* eob = (wq < 4) ? EOe : EOo;
            u64 acc[2][2];
            acc[0][0] = 0ull; acc[0][1] = 0ull;
            acc[1][0] = 0ull; acc[1][1] = 0ull;
            for (int s = 0; s < 16; s++) {
                ulonglong2 t0 = *(const ulonglong2*)(tw + (2 * s) * 16 + s0);
                ulonglong2 t1 = *(const ulonglong2*)(tw + (2 * s + 1) * 16 + s0);
                #pragma unroll
                for (int j = 0; j < 2; j++) {
                    const u64* rp = eob + (yg + 32 * j) * 33 + 2 * s;
                    u64 e0 = rp[0], e1 = rp[1];
                    acc[j][0] = f2fma(e0, t0.x, acc[j][0]);
                    acc[j][1] = f2fma(e0, t0.y, acc[j][1]);
                    acc[j][0] = f2fma(e1, t1.x, acc[j][0]);
                    acc[j][1] = f2fma(e1, t1.y, acc[j][1]);
                }
            }
            {   // x = 32 tail
                ulonglong2 t32 = *(const ulonglong2*)(tw + 32 * 16 + s0);
                #pragma unroll
                for (int j = 0; j < 2; j++) {
                    u64 e32 = eob[(yg + 32 * j) * 33 + 32];
                    acc[j][0] = f2fma(e32, t32.x, acc[j][0]);
                    acc[j][1] = f2fma(e32, t32.y, acc[j][1]);
                }
            }
            #pragma unroll
            for (int j = 0; j < 2; j++) {
                ulonglong2 v; v.x = acc[j][0]; v.y = acc[j][1];
                *(ulonglong2*)(G2 + (y0 + yg + 32 * j) * 16 + s0) = v;
            }
        }
    }
    __syncthreads();

    // ---- in-place y-fold: rows 1..63 -> Gp; rows 65..127 -> Gm ----
    {
        u64 va[4], vb[4];
        #pragma unroll
        for (int j = 0; j < 4; j++) {
            int id = t + 256 * j;
            if (id < 1008) {
                int y = (id >> 4) + 1, s = id & 15;
                va[j] = G2[y * 16 + s];
                vb[j] = G2[(128 - y) * 16 + s];
            }
        }
        __syncthreads();
        #pragma unroll
        for (int j = 0; j < 4; j++) {
            int id = t + 256 * j;
            if (id < 1008) {
                int y = (id >> 4) + 1, s = id & 15;
                float ar, ai, br, bi;
                upk2(va[j], ar, ai); upk2(vb[j], br, bi);
                G2[y * 16 + s]        = pk2(ar + br, ai + bi);
                G2[(64 + y) * 16 + s] = pk2(ar - br, ai - bi);
            }
        }
        __syncthreads();
    }

    // ---- stage 2: C = sum Gp cos(hy), S = sum Gm sin(hy), + embed ----
    if (t < 225) {
        const int s = t % 15, hIdx = t / 15;
        const int w = (s < 8) ? (2 * s + 2) : (2 * s - 13);
        const int wi = w - 2;
        const int h = hIdx + 2;
        const int step = (2 * h) & 127;
        u64 C0 = 0ull, C1 = 0ull, S0 = 0ull, S1 = 0ull;
        int ie = 0, io = h & 127;
        #pragma unroll 4
        for (int u = 0; u < 32; u++) {
            u64 gpe = G2[(2 * u) * 16 + s];
            u64 gme = G2[(64 + 2 * u) * 16 + s];      // u=0 -> sin(0)=0, safe
            ulonglong2 te = cs4[ie];
            C0 = f2fma(gpe, te.x, C0);
            S0 = f2fma(gme, te.y, S0);
            u64 gpo = G2[(2 * u + 1) * 16 + s];
            u64 gmo = G2[(64 + 2 * u + 1) * 16 + s];
            ulonglong2 to = cs4[io];
            C1 = f2fma(gpo, to.x, C1);
            S1 = f2fma(gmo, to.y, S1);
            ie = (ie + step) & 127;
            io = (io + step) & 127;
        }
        C0 = f2fma(G2[64 * 16 + s], cs4[(64 * h) & 127].x, C0);  // y=64 tail

        u64 C = f2add(C0, C1), S = f2add(S0, S1);
        float Cr, Ci, Sr, Si;
        upk2(C, Cr, Ci); upk2(S, Sr, Si);
        const float sc = 1.0f / 128.0f;
        float X1r = (Cr + Si) * sc, X1i = (Ci - Sr) * sc;
        float X2r = (Cr - Si) * sc, X2i = (Ci + Sr) * sc;

        // freq embed
        float al = alpha[c];
        int cb = (c < 384) ? c : (c - 384);
        float dv = expf((float)(cb & ~1) * (-9.210340371976184f / 384.0f));
        float p1, p2;
        if (c < 384) { p1 = (float)h; p2 = (float)(128 - h); }
        else         { p1 = p2 = (float)w; }
        float e1, e2;
        if (c & 1) { e1 = cosf(p1 * dv); e2 = cosf(p2 * dv); }
        else       { e1 = sinf(p1 * dv); e2 = sinf(p2 * dv); }
        X1r += al * e1; X2r += al * e2;

        Xs[hIdx * 15 + wi]        = pk2(X1r, X1i);
        Xs[(29 - hIdx) * 15 + wi] = pk2(X2r, X2i);
    }
    __syncthreads();

    // ---- coalesced contiguous output ----
    {
        u64* dst = g_X + (size_t)bc * 450;
        for (int i = t; i < 450; i += 256) dst[i] = Xs[i];
    }
}

// ===========================================================================
// Kernel 2: complex MLP per block k (96->96->96) + soft shrink.
// grid (57, 8); CTA loops over 2 row-tiles of 32 rows.  Weight loads 128-bit.
// ===========================================================================
#define K2_SMEM 198656

__global__ __launch_bounds__(256) void k_mlp(
    const float* __restrict__ w1r, const float* __restrict__ b1r,
    const float* __restrict__ w1i, const float* __restrict__ b1i,
    const float* __restrict__ w2r, const float* __restrict__ b2r,
    const float* __restrict__ w2i, const float* __restrict__ b2i)
{
    extern __shared__ u64 smu[];
    u64* Xt  = smu;                      // 32*97
    u64* Mid = Xt + 32 * 97;             // 32*97
    float* sW1r = (float*)(Mid + 32 * 97);
    float* sW1i = sW1r + 9216;
    float* sW2r = sW1i + 9216;
    float* sW2i = sW2r + 9216;
    float* sb   = sW2i + 9216;

    const int t  = threadIdx.x;
    const int k  = blockIdx.y;
    const int wo = k * 9216;

    for (int i = t; i < 9216; i += 256) {
        sW1r[i] = w1r[wo + i];
        sW1i[i] = w1i[wo + i];
        sW2r[i] = w2r[wo + i];
        sW2i[i] = w2i[wo + i];
    }
    if (t < 96) {
        sb[t]       = b1r[k * 96 + t];
        sb[96 + t]  = b1i[k * 96 + t];
        sb[192 + t] = b2r[k * 96 + t];
        sb[288 + t] = b2i[k * 96 + t];
    }
    __syncthreads();

    const int r  = t & 31;
    const int cg = t >> 5;
    const int c0 = cg * 12;

    for (int q = 0; q < 2; q++) {
        const int T = blockIdx.x + 57 * q;
        if (T >= 113) break;
        const int r0 = T * 32;

        for (int i = t; i < 32 * 96; i += 256) {
            int rr = i & 31, ci = i >> 5;
            int R = r0 + rr; if (R > 3599) R = 3599;
            int bb = R / 450, m = R - bb * 450;
            Xt[rr * 97 + ci] = g_X[((size_t)(bb * 768 + k * 96 + ci)) * 450 + m];
        }
        __syncthreads();

        u64 ar[6], ai[6];

        // ---- layer 1 ----
        #pragma unroll
        for (int p = 0; p < 6; p++) {
            int cc = c0 + 2 * p;
            float br0 = sb[cc], bi0 = sb[96 + cc];
            float br1 = sb[cc + 1], bi1 = sb[96 + cc + 1];
            ar[p] = pk2(br0 - bi0, br1 - bi1);
            ai[p] = pk2(br0 + bi0, br1 + bi1);
        }
        {
            const u64* xrow = Xt + r * 97;
            #pragma unroll 4
            for (int i = 0; i < 96; i++) {
                float xr, xi; upk2(xrow[i], xr, xi);
                u64 xrr = pk2(xr, xr), xii = pk2(xi, xi), xin = pk2(-xi, -xi);
                const float* wr  = sW1r + i * 96 + c0;
                const float* wii = sW1i + i * 96 + c0;
                ulonglong2 wrq0 = *(const ulonglong2*)(wr);
                ulonglong2 wrq1 = *(const ulonglong2*)(wr + 4);
                ulonglong2 wrq2 = *(const ulonglong2*)(wr + 8);
                ulonglong2 wiq0 = *(const ulonglong2*)(wii);
                ulonglong2 wiq1 = *(const ulonglong2*)(wii + 4);
                ulonglong2 wiq2 = *(const ulonglong2*)(wii + 8);
                u64 wrA[6] = {wrq0.x, wrq0.y, wrq1.x, wrq1.y, wrq2.x, wrq2.y};
                u64 wiA[6] = {wiq0.x, wiq0.y, wiq1.x, wiq1.y, wiq2.x, wiq2.y};
                #pragma unroll
                for (int p = 0; p < 6; p++) {
                    ar[p] = f2fma(xrr, wrA[p], ar[p]);
                    ar[p] = f2fma(xin, wiA[p], ar[p]);
                    ai[p] = f2fma(xii, wrA[p], ai[p]);
                    ai[p] = f2fma(xrr, wiA[p], ai[p]);
                }
            }
        }
        #pragma unroll
        for (int p = 0; p < 6; p++) {
            float r1a, r1b, i1a, i1b;
            upk2(ar[p], r1a, r1b); upk2(ai[p], i1a, i1b);
            Mid[r * 97 + c0 + 2 * p]     = pk2(r1a, i1a);
            Mid[r * 97 + c0 + 2 * p + 1] = pk2(r1b, i1b);
        }
        __syncthreads();

        // ---- layer 2 ----
        #pragma unroll
        for (int p = 0; p < 6; p++) {
            int cc = c0 + 2 * p;
            float br0 = sb[192 + cc], bi0 = sb[288 + cc];
            float br1 = sb[192 + cc + 1], bi1 = sb[288 + cc + 1];
            ar[p] = pk2(br0 - bi0, br1 - bi1);
            ai[p] = pk2(br0 + bi0, br1 + bi1);
        }
        {
            const u64* mrow = Mid + r * 97;
            #pragma unroll 4
            for (int i = 0; i < 96; i++) {
                float xr, xi; upk2(mrow[i], xr, xi);
                u64 xrr = pk2(xr, xr), xii = pk2(xi, xi), xin = pk2(-xi, -xi);
                const float* wr  = sW2r + i * 96 + c0;
                const float* wii = sW2i + i * 96 + c0;
                ulonglong2 wrq0 = *(const ulonglong2*)(wr);
                ulonglong2 wrq1 = *(const ulonglong2*)(wr + 4);
                ulonglong2 wrq2 = *(const ulonglong2*)(wr + 8);
                ulonglong2 wiq0 = *(const ulonglong2*)(wii);
                ulonglong2 wiq1 = *(const ulonglong2*)(wii + 4);
                ulonglong2 wiq2 = *(const ulonglong2*)(wii + 8);
                u64 wrA[6] = {wrq0.x, wrq0.y, wrq1.x, wrq1.y, wrq2.x, wrq2.y};
                u64 wiA[6] = {wiq0.x, wiq0.y, wiq1.x, wiq1.y, wiq2.x, wiq2.y};
                #pragma unroll
                for (int p = 0; p < 6; p++) {
                    ar[p] = f2fma(xrr, wrA[p], ar[p]);
                    ar[p] = f2fma(xin, wiA[p], ar[p]);
                    ai[p] = f2fma(xii, wrA[p], ai[p]);
                    ai[p] = f2fma(xrr, wiA[p], ai[p]);
                }
            }
        }
        __syncthreads();

        #pragma unroll
        for (int p = 0; p < 6; p++) {
            float ra, rb, ia, ib;
            upk2(ar[p], ra, rb); upk2(ai[p], ia, ib);
            Xt[r * 97 + c0 + 2 * p]     = pk2(shrinkf(ra), shrinkf(ia));
            Xt[r * 97 + c0 + 2 * p + 1] = pk2(shrinkf(rb), shrinkf(ib));
        }
        __syncthreads();

        for (int i = t; i < 32 * 96; i += 256) {
            int rr = i & 31, ci = i >> 5;
            int R = r0 + rr;
            if (R < 3600) {
                int bb = R / 450, m = R - bb * 450;
                g_F[((size_t)(bb * 768 + k * 96 + ci)) * 450 + m] = Xt[rr * 97 + ci];
            }
        }
        __syncthreads();
    }
}

// ===========================================================================
// Kernel 3: sparse inverse DFT, x-folded + double y-folded (h-parity).
// Stage-2 p-outer loop (half the accumulators) -> 3 CTAs/SM.  smem 52,688 B.
// ===========================================================================
#define K3_SMEM 52688

__global__ __launch_bounds__(256, 3) void k_inv(float* __restrict__ out)
{
    extern __shared__ u64 smu[];
    u64* Fp = smu;                       // 450
    ulonglong2* cs4 = (ulonglong2*)(smu + 450);
    u64* Pc = smu + 706;                 // [hi*66 + x]
    u64* Ps = smu + 2686;
    float* Ua = (float*)(smu + 4666);    // [hp*128 + x], pre-scaled by 1/64
    float* Ub = (float*)(smu + 5626);

    const int t  = threadIdx.x;
    const int bc = blockIdx.x;

    if (t < 128) {
        float cv, sv;
        sincosf(t * PI2_128, &sv, &cv);
        ulonglong2 e; e.x = pk2(cv, cv); e.y = pk2(sv, sv);
        cs4[t] = e;
    }
    {
        const u64* srcF = g_F + (size_t)bc * 450;
        for (int i = t; i < 450; i += 256) Fp[i] = srcF[i];
    }
    __syncthreads();

    // ---- stage 1: Pc/Ps[hi][x] = Sum_w F * (cos, sin)((w+2) x), x=0..64 ----
    if (t < 240) {
        const int hi = t % 30, xg = t / 30;
        u64 F[15];
        #pragma unroll
        for (int w = 0; w < 15; w++) F[w] = Fp[hi * 15 + w];
        for (int q = 0; q < 9; q++) {
            int xx = xg + 8 * q;
            if (xx > 64) break;
            const int stp = (2 * xx) & 127;
            u64 cA = 0ull, sA = 0ull, cB = 0ull, sB = 0ull;
            int iA = stp;
            int iB = (3 * xx) & 127;
            #pragma unroll
            for (int w = 0; w < 15; w += 2) {
                ulonglong2 tb = cs4[iA];
                cA = f2fma(F[w], tb.x, cA);
                sA = f2fma(F[w], tb.y, sA);
                iA = (iA + stp) & 127;
            }
            #pragma unroll
            for (int w = 1; w < 15; w += 2) {
                ulonglong2 tb = cs4[iB];
                cB = f2fma(F[w], tb.x, cB);
                sB = f2fma(F[w], tb.y, sB);
                iB = (iB + stp) & 127;
            }
            Pc[hi * 66 + xx] = f2add(cA, cB);
            Ps[hi * 66 + xx] = f2add(sA, sB);
        }
    }
    __syncthreads();

    // ---- combine: fold h-pairs + reconstruct x and 128-x (scaled 1/64) ----
    for (int idx = t; idx < 15 * 65; idx += 256) {
        int hp = idx / 65, xx = idx - hp * 65;
        const float sc = 1.0f / 64.0f;
        float c1r, c1i, s1r, s1i, c2r, c2i, s2r, s2i;
        upk2(Pc[hp * 66 + xx], c1r, c1i);
        upk2(Ps[hp * 66 + xx], s1r, s1i);
        upk2(Pc[(29 - hp) * 66 + xx], c2r, c2i);
        upk2(Ps[(29 - hp) * 66 + xx], s2r, s2i);
        float p1re = c1r - s1i, p1im = c1i + s1r;
        float p2re = c2r - s2i, p2im = c2i + s2r;
        Ua[hp * 128 + xx] = (p1re + p2re) * sc;
        Ub[hp * 128 + xx] = (p1im - p2im) * sc;
        if (xx >= 1 && xx <= 63) {
            float m1re = c1r + s1i, m1im = c1i - s1r;
            float m2re = c2r + s2i, m2im = c2i - s2r;
            Ua[hp * 128 + 128 - xx] = (m1re + m2re) * sc;
            Ub[hp * 128 + 128 - xx] = (m1im - m2im) * sc;
        }
    }
    __syncthreads();

    // ---- stage 2: h-parity split, float4 x-quads, p-outer (low regs) ----
    {
        const int xg = t & 15;            // quad x = 4*xg + 64*p
        const int yg = t >> 4;            // y in {yg, yg+16}
        float* outp = out + (size_t)bc * 16384 + 4 * xg;

        #pragma unroll
        for (int p = 0; p < 2; p++) {
            ulonglong2 Ae[2], Ao[2], Be[2], Bo[2];
            #pragma unroll
            for (int yi = 0; yi < 2; yi++) {
                Ae[yi].x = 0ull; Ae[yi].y = 0ull;
                Ao[yi].x = 0ull; Ao[yi].y = 0ull;
                Be[yi].x = 0ull; Be[yi].y = 0ull;
                Bo[yi].x = 0ull; Bo[yi].y = 0ull;
            }
            const int xo = 4 * xg + 64 * p;

            #pragma unroll
            for (int hp = 0; hp < 15; hp += 2) {      // even h = hp+2
                const int h = hp + 2;
                ulonglong2 ua = *(const ulonglong2*)(Ua + hp * 128 + xo);
                ulonglong2 ub = *(const ulonglong2*)(Ub + hp * 128 + xo);
                #pragma unroll
                for (int yi = 0; yi < 2; yi++) {
                    ulonglong2 tb = cs4[(h * (yg + 16 * yi)) & 127];
                    Ae[yi].x = f2fma(ua.x, tb.x, Ae[yi].x);
                    Ae[yi].y = f2fma(ua.y, tb.x, Ae[yi].y);
                    Be[yi].x = f2fma(ub.x, tb.y, Be[yi].x);
                    Be[yi].y = f2fma(ub.y, tb.y, Be[yi].y);
                }
            }
            #pragma unroll
            for (int hp = 1; hp < 15; hp += 2) {      // odd h
                const int h = hp + 2;
                ulonglong2 ua = *(const ulonglong2*)(Ua + hp * 128 + xo);
                ulonglong2 ub = *(const ulonglong2*)(Ub + hp * 128 + xo);
                #pragma unroll
                for (int yi = 0; yi < 2; yi++) {
                    ulonglong2 tb = cs4[(h * (yg + 16 * yi)) & 127];
                    Ao[yi].x = f2fma(ua.x, tb.x, Ao[yi].x);
                    Ao[yi].y = f2fma(ua.y, tb.x, Ao[yi].y);
                    Bo[yi].x = f2fma(ub.x, tb.y, Bo[yi].x);
                    Bo[yi].y = f2fma(ub.y, tb.y, Bo[yi].y);
                }
            }

            #pragma unroll
            for (int yi = 0; yi < 2; yi++) {
                int y = yg + 16 * yi;
                u64 Px = f2add(Ae[yi].x, Ao[yi].x);
                u64 Py = f2add(Ae[yi].y, Ao[yi].y);
                u64 Qx = f2sub(Ae[yi].x, Ao[yi].x);
                u64 Qy = f2sub(Ae[yi].y, Ao[yi].y);
                u64 Rx = f2add(Be[yi].x, Bo[yi].x);
                u64 Ry = f2add(Be[yi].y, Bo[yi].y);
                u64 Sx = f2sub(Be[yi].x, Bo[yi].x);
                u64 Sy = f2sub(Be[yi].y, Bo[yi].y);
                float a0, a1, a2, a3;
                // out[y] = P - R
                upk2(f2sub(Px, Rx), a0, a1); upk2(f2sub(Py, Ry), a2, a3);
                *(float4*)(outp + y * 128 + 64 * p) = make_float4(a0, a1, a2, a3);
                // out[64-y] = Q + S
                upk2(f2add(Qx, Sx), a0, a1); upk2(f2add(Qy, Sy), a2, a3);
                *(float4*)(outp + (64 - y) * 128 + 64 * p) = make_float4(a0, a1, a2, a3);
                if (y > 0) {
                    // out[64+y] = Q - S
                    upk2(f2sub(Qx, Sx), a0, a1); upk2(f2sub(Qy, Sy), a2, a3);
                    *(float4*)(outp + (64 + y) * 128 + 64 * p) = make_float4(a0, a1, a2, a3);
                    // out[128-y] = P + R
                    upk2(f2add(Px, Rx), a0, a1); upk2(f2add(Py, Ry), a2, a3);
                    *(float4*)(outp + (128 - y) * 128 + 64 * p) = make_float4(a0, a1, a2, a3);
                }
            }
        }
    }

    // ---- rows y = 32 and y = 96 ----
    if (t < 64) {
        u64 Se = 0ull, So = 0ull;
        #pragma unroll
        for (int hp = 0; hp < 15; hp++) {
            if ((hp & 1) == 0) {         // even h: cos(32 h th) = (-1)^(hp/2+1)
                float sg = ((hp >> 1) & 1) ? 1.0f : -1.0f;
                u64 ua = *(const u64*)(Ua + hp * 128 + 2 * t);
                Se = f2fma(ua, pk2(sg, sg), Se);
            } else {                     // odd h: sin(32 h th) = (-1)^((hp+1)/2)
                float sg = (((hp + 1) >> 1) & 1) ? -1.0f : 1.0f;
                u64 ub = *(const u64*)(Ub + hp * 128 + 2 * t);
                So = f2fma(ub, pk2(sg, sg), So);
            }
        }
        float a, bv;
        upk2(f2sub(Se, So), a, bv);
        *(float2*)(out + (size_t)bc * 16384 + 32 * 128 + 2 * t) =
            make_float2(a, bv);
        upk2(f2add(Se, So), a, bv);
        *(float2*)(out + (size_t)bc * 16384 + 96 * 128 + 2 * t) =
            make_float2(a, bv);
    }
}

// ===========================================================================
extern "C" void kernel_launch(void* const* d_in, const int* in_sizes, int n_in,
                              void* d_out, int out_size)
{
    const float* x     = (const float*)d_in[0];
    const float* alpha = (const float*)d_in[1];
    const float* w1r   = (const float*)d_in[2];
    const float* b1r   = (const float*)d_in[3];
    const float* w1i   = (const float*)d_in[4];
    const float* b1i   = (const float*)d_in[5];
    const float* w2r   = (const float*)d_in[6];
    const float* b2r   = (const float*)d_in[7];
    const float* w2i   = (const float*)d_in[8];
    const float* b2i   = (const float*)d_in[9];
    float* out = (float*)d_out;

    cudaFuncSetAttribute(k_fwd, cudaFuncAttributeMaxDynamicSharedMemorySize, K1_SMEM);
    cudaFuncSetAttribute(k_mlp, cudaFuncAttributeMaxDynamicSharedMemorySize, K2_SMEM);
    cudaFuncSetAttribute(k_inv, cudaFuncAttributeMaxDynamicSharedMemorySize, K3_SMEM);

    k_fwd<<<6144, 256, K1_SMEM>>>(x, alpha);
    k_mlp<<<dim3(57, 8), 256, K2_SMEM>>>(w1r, b1r, w1i, b1i, w2r, b2r, w2i, b2i);
    k_inv<<<6144, 256, K3_SMEM>>>(out);
}

// round 15
// speedup vs baseline: 1.1679x; 1.1679x over previous
#include <cuda_runtime.h>
#include <math.h>

typedef unsigned long long u64;

#define PI2_128 0.04908738521234052f   // 2*pi/128

__device__ __forceinline__ u64 pk2(float lo, float hi) {
    u64 r; asm("mov.b64 %0,{%1,%2};" : "=l"(r) : "f"(lo), "f"(hi)); return r;
}
__device__ __forceinline__ void upk2(u64 a, float& lo, float& hi) {
    asm("mov.b64 {%0,%1},%2;" : "=f"(lo), "=f"(hi) : "l"(a));
}
__device__ __forceinline__ u64 f2fma(u64 a, u64 b, u64 c) {
    u64 d; asm("fma.rn.f32x2 %0,%1,%2,%3;" : "=l"(d) : "l"(a), "l"(b), "l"(c)); return d;
}
__device__ __forceinline__ u64 f2add(u64 a, u64 b) {
    u64 d; asm("add.rn.f32x2 %0,%1,%2;" : "=l"(d) : "l"(a), "l"(b)); return d;
}
__device__ __forceinline__ u64 f2sub(u64 a, u64 b) {
    u64 d; asm("sub.rn.f32x2 %0,%1,%2;" : "=l"(d) : "l"(a), "l"(b)); return d;
}
__device__ __forceinline__ float shrinkf(float v) {
    float a = fabsf(v) - 0.01f;
    return a > 0.f ? copysignf(a, v) : 0.f;
}

// Scratch in [bc][450] contiguous layout: element = (re,im) packed u64.
__device__ u64 g_X[6144 * 450];
__device__ u64 g_F[6144 * 450];

// ===========================================================================
// Kernel 1: forward pruned DFT, double-folded in x, folded in y.
// One CTA per (b,c).  smem 56,576 B -> 4 CTAs/SM.  (R13 version, 241 us)
// ===========================================================================
#define K1_SMEM 56576

__global__ __launch_bounds__(256, 4) void k_fwd(const float* __restrict__ x,
                                                const float* __restrict__ alpha)
{
    extern __shared__ u64 smu[];
    u64* EOe = smu;                      // [yl*33 + x], yl 0..63
    u64* EOo = smu + 2112;
    u64* Xs  = smu;                      // overlays EO after stage 1
    u64* tw  = smu + 4224;               // [x*16 + slot]
    u64* G2  = smu + 4768;               // [y*16 + slot]
    ulonglong2* cs4 = (ulonglong2*)(smu + 6816);

    const int t  = threadIdx.x;
    const int bc = blockIdx.x;
    const int b  = bc / 768, c = bc - b * 768;

    // ---- base trig table ----
    if (t < 128) {
        float cv, sv;
        sincosf(t * PI2_128, &sv, &cv);
        ulonglong2 e; e.x = pk2(cv, cv); e.y = pk2(sv, sv);
        cs4[t] = e;
    }
    __syncthreads();

    // ---- tw table: (cos(wx), -sin(wx)); slots 0..7 even w, 8..14 odd ----
    for (int i = t; i < 33 * 16; i += 256) {
        int xx = i >> 4, s = i & 15;
        if (s < 15) {
            int w = (s < 8) ? (2 * s + 2) : (2 * s - 13);
            ulonglong2 e = cs4[(w * xx) & 127];
            float cv, dum, sv;
            upk2(e.x, cv, dum);
            upk2(e.y, sv, dum);
            tw[i] = pk2(cv, -sv);
        } else {
            tw[i] = 0ull;
        }
    }

    // ---- 2 chunks of 64 rows: load + double x-fold -> EO, W-DFT -> G2 ----
    const int wrp = t >> 5, l = t & 31;
    const float* src = x + (size_t)bc * 16384;
    for (int ck = 0; ck < 2; ck++) {
        const int y0 = ck * 64;
        if (ck > 0) __syncthreads();     // EO reuse barrier
        for (int i = 0; i < 8; i++) {
            int yl = wrp * 8 + i;
            const float* row = src + (y0 + yl) * 128;
            float a = row[l];
            float u = row[32 + l];
            float m = row[64 + l];
            float q = row[96 + l];
            float Bu = __shfl_sync(0xffffffffu, u, (32 - l) & 31);
            float Dq = __shfl_sync(0xffffffffu, q, (32 - l) & 31);
            float v32 = __shfl_sync(0xffffffffu, u, 0);
            float v96 = __shfl_sync(0xffffffffu, q, 0);
            float Ep, Em, Om, Op;
            if (l == 0) {
                Ep = a + m;  Em = a - m;  Om = 0.f;  Op = 0.f;
            } else {
                float AD = a + Dq, ADm = a - Dq;
                float BC = Bu + m, CBm = m - Bu;
                Ep = AD + BC;  Em = AD - BC;
                Om = ADm + CBm; Op = ADm - CBm;
            }
            EOe[yl * 33 + l] = pk2(Ep, Om);
            EOo[yl * 33 + l] = pk2(Em, Op);
            if (l == 0) {
                u64 e32 = pk2(v32 + v96, v32 - v96);
                EOe[yl * 33 + 32] = e32;
                EOo[yl * 33 + 32] = e32;
            }
        }
        __syncthreads();

        // stage 1: thread = (2 rows, 2 slots); x loop 0..31 + x=32 tail
        {
            const int wq = t & 7;
            const int yg = t >> 3;
            const int s0 = wq * 2;
            const u64* eob = (wq < 4) ? EOe : EOo;
            u64 acc[2][2];
            acc[0][0] = 0ull; acc[0][1] = 0ull;
            acc[1][0] = 0ull; acc[1][1] = 0ull;
            for (int s = 0; s < 16; s++) {
                ulonglong2 t0 = *(const ulonglong2*)(tw + (2 * s) * 16 + s0);
                ulonglong2 t1 = *(const ulonglong2*)(tw + (2 * s + 1) * 16 + s0);
                #pragma unroll
                for (int j = 0; j < 2; j++) {
                    const u64* rp = eob + (yg + 32 * j) * 33 + 2 * s;
                    u64 e0 = rp[0], e1 = rp[1];
                    acc[j][0] = f2fma(e0, t0.x, acc[j][0]);
                    acc[j][1] = f2fma(e0, t0.y, acc[j][1]);
                    acc[j][0] = f2fma(e1, t1.x, acc[j][0]);
                    acc[j][1] = f2fma(e1, t1.y, acc[j][1]);
                }
            }
            {   // x = 32 tail
                ulonglong2 t32 = *(const ulonglong2*)(tw + 32 * 16 + s0);
                #pragma unroll
                for (int j = 0; j < 2; j++) {
                    u64 e32 = eob[(yg + 32 * j) * 33 + 32];
                    acc[j][0] = f2fma(e32, t32.x, acc[j][0]);
                    acc[j][1] = f2fma(e32, t32.y, acc[j][1]);
                }
            }
            #pragma unroll
            for (int j = 0; j < 2; j++) {
                ulonglong2 v; v.x = acc[j][0]; v.y = acc[j][1];
                *(ulonglong2*)(G2 + (y0 + yg + 32 * j) * 16 + s0) = v;
            }
        }
    }
    __syncthreads();

    // ---- in-place y-fold: rows 1..63 -> Gp; rows 65..127 -> Gm ----
    {
        u64 va[4], vb[4];
        #pragma unroll
        for (int j = 0; j < 4; j++) {
            int id = t + 256 * j;
            if (id < 1008) {
                int y = (id >> 4) + 1, s = id & 15;
                va[j] = G2[y * 16 + s];
                vb[j] = G2[(128 - y) * 16 + s];
            }
        }
        __syncthreads();
        #pragma unroll
        for (int j = 0; j < 4; j++) {
            int id = t + 256 * j;
            if (id < 1008) {
                int y = (id >> 4) + 1, s = id & 15;
                float ar, ai, br, bi;
                upk2(va[j], ar, ai); upk2(vb[j], br, bi);
                G2[y * 16 + s]        = pk2(ar + br, ai + bi);
                G2[(64 + y) * 16 + s] = pk2(ar - br, ai - bi);
            }
        }
        __syncthreads();
    }

    // ---- stage 2: C = sum Gp cos(hy), S = sum Gm sin(hy), + embed ----
    if (t < 225) {
        const int s = t % 15, hIdx = t / 15;
        const int w = (s < 8) ? (2 * s + 2) : (2 * s - 13);
        const int wi = w - 2;
        const int h = hIdx + 2;
        const int step = (2 * h) & 127;
        u64 C0 = 0ull, C1 = 0ull, S0 = 0ull, S1 = 0ull;
        int ie = 0, io = h & 127;
        #pragma unroll 4
        for (int u = 0; u < 32; u++) {
            u64 gpe = G2[(2 * u) * 16 + s];
            u64 gme = G2[(64 + 2 * u) * 16 + s];
            ulonglong2 te = cs4[ie];
            C0 = f2fma(gpe, te.x, C0);
            S0 = f2fma(gme, te.y, S0);
            u64 gpo = G2[(2 * u + 1) * 16 + s];
            u64 gmo = G2[(64 + 2 * u + 1) * 16 + s];
            ulonglong2 to = cs4[io];
            C1 = f2fma(gpo, to.x, C1);
            S1 = f2fma(gmo, to.y, S1);
            ie = (ie + step) & 127;
            io = (io + step) & 127;
        }
        C0 = f2fma(G2[64 * 16 + s], cs4[(64 * h) & 127].x, C0);

        u64 C = f2add(C0, C1), S = f2add(S0, S1);
        float Cr, Ci, Sr, Si;
        upk2(C, Cr, Ci); upk2(S, Sr, Si);
        const float sc = 1.0f / 128.0f;
        float X1r = (Cr + Si) * sc, X1i = (Ci - Sr) * sc;
        float X2r = (Cr - Si) * sc, X2i = (Ci + Sr) * sc;

        // freq embed
        float al = alpha[c];
        int cb = (c < 384) ? c : (c - 384);
        float dv = expf((float)(cb & ~1) * (-9.210340371976184f / 384.0f));
        float p1, p2;
        if (c < 384) { p1 = (float)h; p2 = (float)(128 - h); }
        else         { p1 = p2 = (float)w; }
        float e1, e2;
        if (c & 1) { e1 = cosf(p1 * dv); e2 = cosf(p2 * dv); }
        else       { e1 = sinf(p1 * dv); e2 = sinf(p2 * dv); }
        X1r += al * e1; X2r += al * e2;

        Xs[hIdx * 15 + wi]        = pk2(X1r, X1i);
        Xs[(29 - hIdx) * 15 + wi] = pk2(X2r, X2i);
    }
    __syncthreads();

    {
        u64* dst = g_X + (size_t)bc * 450;
        for (int i = t; i < 450; i += 256) dst[i] = Xs[i];
    }
}

// ===========================================================================
// Kernel 2: complex MLP per block k (96->96->96) + soft shrink. (unchanged)
// ===========================================================================
#define K2_SMEM 198656

__global__ __launch_bounds__(256) void k_mlp(
    const float* __restrict__ w1r, const float* __restrict__ b1r,
    const float* __restrict__ w1i, const float* __restrict__ b1i,
    const float* __restrict__ w2r, const float* __restrict__ b2r,
    const float* __restrict__ w2i, const float* __restrict__ b2i)
{
    extern __shared__ u64 smu[];
    u64* Xt  = smu;                      // 32*97
    u64* Mid = Xt + 32 * 97;             // 32*97
    float* sW1r = (float*)(Mid + 32 * 97);
    float* sW1i = sW1r + 9216;
    float* sW2r = sW1i + 9216;
    float* sW2i = sW2r + 9216;
    float* sb   = sW2i + 9216;

    const int t  = threadIdx.x;
    const int k  = blockIdx.y;
    const int wo = k * 9216;

    for (int i = t; i < 9216; i += 256) {
        sW1r[i] = w1r[wo + i];
        sW1i[i] = w1i[wo + i];
        sW2r[i] = w2r[wo + i];
        sW2i[i] = w2i[wo + i];
    }
    if (t < 96) {
        sb[t]       = b1r[k * 96 + t];
        sb[96 + t]  = b1i[k * 96 + t];
        sb[192 + t] = b2r[k * 96 + t];
        sb[288 + t] = b2i[k * 96 + t];
    }
    __syncthreads();

    const int r  = t & 31;
    const int cg = t >> 5;
    const int c0 = cg * 12;

    for (int q = 0; q < 2; q++) {
        const int T = blockIdx.x + 57 * q;
        if (T >= 113) break;
        const int r0 = T * 32;

        for (int i = t; i < 32 * 96; i += 256) {
            int rr = i & 31, ci = i >> 5;
            int R = r0 + rr; if (R > 3599) R = 3599;
            int bb = R / 450, m = R - bb * 450;
            Xt[rr * 97 + ci] = g_X[((size_t)(bb * 768 + k * 96 + ci)) * 450 + m];
        }
        __syncthreads();

        u64 ar[6], ai[6];

        // ---- layer 1 ----
        #pragma unroll
        for (int p = 0; p < 6; p++) {
            int cc = c0 + 2 * p;
            float br0 = sb[cc], bi0 = sb[96 + cc];
            float br1 = sb[cc + 1], bi1 = sb[96 + cc + 1];
            ar[p] = pk2(br0 - bi0, br1 - bi1);
            ai[p] = pk2(br0 + bi0, br1 + bi1);
        }
        {
            const u64* xrow = Xt + r * 97;
            #pragma unroll 4
            for (int i = 0; i < 96; i++) {
                float xr, xi; upk2(xrow[i], xr, xi);
                u64 xrr = pk2(xr, xr), xii = pk2(xi, xi), xin = pk2(-xi, -xi);
                const float* wr  = sW1r + i * 96 + c0;
                const float* wii = sW1i + i * 96 + c0;
                ulonglong2 wrq0 = *(const ulonglong2*)(wr);
                ulonglong2 wrq1 = *(const ulonglong2*)(wr + 4);
                ulonglong2 wrq2 = *(const ulonglong2*)(wr + 8);
                ulonglong2 wiq0 = *(const ulonglong2*)(wii);
                ulonglong2 wiq1 = *(const ulonglong2*)(wii + 4);
                ulonglong2 wiq2 = *(const ulonglong2*)(wii + 8);
                u64 wrA[6] = {wrq0.x, wrq0.y, wrq1.x, wrq1.y, wrq2.x, wrq2.y};
                u64 wiA[6] = {wiq0.x, wiq0.y, wiq1.x, wiq1.y, wiq2.x, wiq2.y};
                #pragma unroll
                for (int p = 0; p < 6; p++) {
                    ar[p] = f2fma(xrr, wrA[p], ar[p]);
                    ar[p] = f2fma(xin, wiA[p], ar[p]);
                    ai[p] = f2fma(xii, wrA[p], ai[p]);
                    ai[p] = f2fma(xrr, wiA[p], ai[p]);
                }
            }
        }
        #pragma unroll
        for (int p = 0; p < 6; p++) {
            float r1a, r1b, i1a, i1b;
            upk2(ar[p], r1a, r1b); upk2(ai[p], i1a, i1b);
            Mid[r * 97 + c0 + 2 * p]     = pk2(r1a, i1a);
            Mid[r * 97 + c0 + 2 * p + 1] = pk2(r1b, i1b);
        }
        __syncthreads();

        // ---- layer 2 ----
        #pragma unroll
        for (int p = 0; p < 6; p++) {
            int cc = c0 + 2 * p;
            float br0 = sb[192 + cc], bi0 = sb[288 + cc];
            float br1 = sb[192 + cc + 1], bi1 = sb[288 + cc + 1];
            ar[p] = pk2(br0 - bi0, br1 - bi1);
            ai[p] = pk2(br0 + bi0, br1 + bi1);
        }
        {
            const u64* mrow = Mid + r * 97;
            #pragma unroll 4
            for (int i = 0; i < 96; i++) {
                float xr, xi; upk2(mrow[i], xr, xi);
                u64 xrr = pk2(xr, xr), xii = pk2(xi, xi), xin = pk2(-xi, -xi);
                const float* wr  = sW2r + i * 96 + c0;
                const float* wii = sW2i + i * 96 + c0;
                ulonglong2 wrq0 = *(const ulonglong2*)(wr);
                ulonglong2 wrq1 = *(const ulonglong2*)(wr + 4);
                ulonglong2 wrq2 = *(const ulonglong2*)(wr + 8);
                ulonglong2 wiq0 = *(const ulonglong2*)(wii);
                ulonglong2 wiq1 = *(const ulonglong2*)(wii + 4);
                ulonglong2 wiq2 = *(const ulonglong2*)(wii + 8);
                u64 wrA[6] = {wrq0.x, wrq0.y, wrq1.x, wrq1.y, wrq2.x, wrq2.y};
                u64 wiA[6] = {wiq0.x, wiq0.y, wiq1.x, wiq1.y, wiq2.x, wiq2.y};
                #pragma unroll
                for (int p = 0; p < 6; p++) {
                    ar[p] = f2fma(xrr, wrA[p], ar[p]);
                    ar[p] = f2fma(xin, wiA[p], ar[p]);
                    ai[p] = f2fma(xii, wrA[p], ai[p]);
                    ai[p] = f2fma(xrr, wiA[p], ai[p]);
                }
            }
        }
        __syncthreads();

        #pragma unroll
        for (int p = 0; p < 6; p++) {
            float ra, rb, ia, ib;
            upk2(ar[p], ra, rb); upk2(ai[p], ia, ib);
            Xt[r * 97 + c0 + 2 * p]     = pk2(shrinkf(ra), shrinkf(ia));
            Xt[r * 97 + c0 + 2 * p + 1] = pk2(shrinkf(rb), shrinkf(ib));
        }
        __syncthreads();

        for (int i = t; i < 32 * 96; i += 256) {
            int rr = i & 31, ci = i >> 5;
            int R = r0 + rr;
            if (R < 3600) {
                int bb = R / 450, m = R - bb * 450;
                g_F[((size_t)(bb * 768 + k * 96 + ci)) * 450 + m] = Xt[rr * 97 + ci];
            }
        }
        __syncthreads();
    }
}

// ===========================================================================
// Kernel 3: sparse inverse DFT, x-folded + double y-folded (h-parity).
// R12 configuration: 2 CTAs/SM (no reg cap spills), p-inner float4 quads.
// ===========================================================================
#define K3_SMEM 52688

__global__ __launch_bounds__(256, 2) void k_inv(float* __restrict__ out)
{
    extern __shared__ u64 smu[];
    u64* Fp = smu;                       // 450
    ulonglong2* cs4 = (ulonglong2*)(smu + 450);
    u64* Pc = smu + 706;                 // [hi*66 + x]
    u64* Ps = smu + 2686;
    float* Ua = (float*)(smu + 4666);    // [hp*128 + x], pre-scaled by 1/64
    float* Ub = (float*)(smu + 5626);

    const int t  = threadIdx.x;
    const int bc = blockIdx.x;

    if (t < 128) {
        float cv, sv;
        sincosf(t * PI2_128, &sv, &cv);
        ulonglong2 e; e.x = pk2(cv, cv); e.y = pk2(sv, sv);
        cs4[t] = e;
    }
    {
        const u64* srcF = g_F + (size_t)bc * 450;
        for (int i = t; i < 450; i += 256) Fp[i] = srcF[i];
    }
    __syncthreads();

    // ---- stage 1: Pc/Ps[hi][x] = Sum_w F * (cos, sin)((w+2) x), x=0..64 ----
    if (t < 240) {
        const int hi = t % 30, xg = t / 30;
        u64 F[15];
        #pragma unroll
        for (int w = 0; w < 15; w++) F[w] = Fp[hi * 15 + w];
        for (int q = 0; q < 9; q++) {
            int xx = xg + 8 * q;
            if (xx > 64) break;
            const int stp = (2 * xx) & 127;
            u64 cA = 0ull, sA = 0ull, cB = 0ull, sB = 0ull;
            int iA = stp;
            int iB = (3 * xx) & 127;
            #pragma unroll
            for (int w = 0; w < 15; w += 2) {
                ulonglong2 tb = cs4[iA];
                cA = f2fma(F[w], tb.x, cA);
                sA = f2fma(F[w], tb.y, sA);
                iA = (iA + stp) & 127;
            }
            #pragma unroll
            for (int w = 1; w < 15; w += 2) {
                ulonglong2 tb = cs4[iB];
                cB = f2fma(F[w], tb.x, cB);
                sB = f2fma(F[w], tb.y, sB);
                iB = (iB + stp) & 127;
            }
            Pc[hi * 66 + xx] = f2add(cA, cB);
            Ps[hi * 66 + xx] = f2add(sA, sB);
        }
    }
    __syncthreads();

    // ---- combine: fold h-pairs + reconstruct x and 128-x (scaled 1/64) ----
    for (int idx = t; idx < 15 * 65; idx += 256) {
        int hp = idx / 65, xx = idx - hp * 65;
        const float sc = 1.0f / 64.0f;
        float c1r, c1i, s1r, s1i, c2r, c2i, s2r, s2i;
        upk2(Pc[hp * 66 + xx], c1r, c1i);
        upk2(Ps[hp * 66 + xx], s1r, s1i);
        upk2(Pc[(29 - hp) * 66 + xx], c2r, c2i);
        upk2(Ps[(29 - hp) * 66 + xx], s2r, s2i);
        float p1re = c1r - s1i, p1im = c1i + s1r;
        float p2re = c2r - s2i, p2im = c2i + s2r;
        Ua[hp * 128 + xx] = (p1re + p2re) * sc;
        Ub[hp * 128 + xx] = (p1im - p2im) * sc;
        if (xx >= 1 && xx <= 63) {
            float m1re = c1r + s1i, m1im = c1i - s1r;
            float m2re = c2r + s2i, m2im = c2i - s2r;
            Ua[hp * 128 + 128 - xx] = (m1re + m2re) * sc;
            Ub[hp * 128 + 128 - xx] = (m1im - m2im) * sc;
        }
    }
    __syncthreads();

    // ---- stage 2: h-parity split, float4 x-quads -> 4 output rows per y ----
    {
        const int xg = t & 15;            // quads: x = 4*xg + 64*p, p=0,1
        const int yg = t >> 4;            // y in {yg, yg+16}
        ulonglong2 Ae[2][2], Ao[2][2], Be[2][2], Bo[2][2];
        #pragma unroll
        for (int yi = 0; yi < 2; yi++)
            #pragma unroll
            for (int p = 0; p < 2; p++) {
                Ae[yi][p].x = 0ull; Ae[yi][p].y = 0ull;
                Ao[yi][p].x = 0ull; Ao[yi][p].y = 0ull;
                Be[yi][p].x = 0ull; Be[yi][p].y = 0ull;
                Bo[yi][p].x = 0ull; Bo[yi][p].y = 0ull;
            }

        #pragma unroll
        for (int hp = 0; hp < 15; hp += 2) {      // even h = hp+2
            const int h = hp + 2;
            ulonglong2 ua[2], ub[2];
            #pragma unroll
            for (int p = 0; p < 2; p++) {
                ua[p] = *(const ulonglong2*)(Ua + hp * 128 + 4 * xg + 64 * p);
                ub[p] = *(const ulonglong2*)(Ub + hp * 128 + 4 * xg + 64 * p);
            }
            #pragma unroll
            for (int yi = 0; yi < 2; yi++) {
                ulonglong2 tb = cs4[(h * (yg + 16 * yi)) & 127];
                #pragma unroll
                for (int p = 0; p < 2; p++) {
                    Ae[yi][p].x = f2fma(ua[p].x, tb.x, Ae[yi][p].x);
                    Ae[yi][p].y = f2fma(ua[p].y, tb.x, Ae[yi][p].y);
                    Be[yi][p].x = f2fma(ub[p].x, tb.y, Be[yi][p].x);
                    Be[yi][p].y = f2fma(ub[p].y, tb.y, Be[yi][p].y);
                }
            }
        }
        #pragma unroll
        for (int hp = 1; hp < 15; hp += 2) {      // odd h
            const int h = hp + 2;
            ulonglong2 ua[2], ub[2];
            #pragma unroll
            for (int p = 0; p < 2; p++) {
                ua[p] = *(const ulonglong2*)(Ua + hp * 128 + 4 * xg + 64 * p);
                ub[p] = *(const ulonglong2*)(Ub + hp * 128 + 4 * xg + 64 * p);
            }
            #pragma unroll
            for (int yi = 0; yi < 2; yi++) {
                ulonglong2 tb = cs4[(h * (yg + 16 * yi)) & 127];
                #pragma unroll
                for (int p = 0; p < 2; p++) {
                    Ao[yi][p].x = f2fma(ua[p].x, tb.x, Ao[yi][p].x);
                    Ao[yi][p].y = f2fma(ua[p].y, tb.x, Ao[yi][p].y);
                    Bo[yi][p].x = f2fma(ub[p].x, tb.y, Bo[yi][p].x);
                    Bo[yi][p].y = f2fma(ub[p].y, tb.y, Bo[yi][p].y);
                }
            }
        }

        float* outp = out + (size_t)bc * 16384 + 4 * xg;
        #pragma unroll
        for (int yi = 0; yi < 2; yi++) {
            int y = yg + 16 * yi;
            #pragma unroll
            for (int p = 0; p < 2; p++) {
                u64 Px = f2add(Ae[yi][p].x, Ao[yi][p].x);
                u64 Py = f2add(Ae[yi][p].y, Ao[yi][p].y);
                u64 Qx = f2sub(Ae[yi][p].x, Ao[yi][p].x);
                u64 Qy = f2sub(Ae[yi][p].y, Ao[yi][p].y);
                u64 Rx = f2add(Be[yi][p].x, Bo[yi][p].x);
                u64 Ry = f2add(Be[yi][p].y, Bo[yi][p].y);
                u64 Sx = f2sub(Be[yi][p].x, Bo[yi][p].x);
                u64 Sy = f2sub(Be[yi][p].y, Bo[yi][p].y);
                float a0, a1, a2, a3;
                // out[y] = P - R
                upk2(f2sub(Px, Rx), a0, a1); upk2(f2sub(Py, Ry), a2, a3);
                *(float4*)(outp + y * 128 + 64 * p) = make_float4(a0, a1, a2, a3);
                // out[64-y] = Q + S
                upk2(f2add(Qx, Sx), a0, a1); upk2(f2add(Qy, Sy), a2, a3);
                *(float4*)(outp + (64 - y) * 128 + 64 * p) = make_float4(a0, a1, a2, a3);
                if (y > 0) {
                    // out[64+y] = Q - S
                    upk2(f2sub(Qx, Sx), a0, a1); upk2(f2sub(Qy, Sy), a2, a3);
                    *(float4*)(outp + (64 + y) * 128 + 64 * p) = make_float4(a0, a1, a2, a3);
                    // out[128-y] = P + R
                    upk2(f2add(Px, Rx), a0, a1); upk2(f2add(Py, Ry), a2, a3);
                    *(float4*)(outp + (128 - y) * 128 + 64 * p) = make_float4(a0, a1, a2, a3);
                }
            }
        }
    }

    // ---- rows y = 32 and y = 96 ----
    if (t < 64) {
        u64 Se = 0ull, So = 0ull;
        #pragma unroll
        for (int hp = 0; hp < 15; hp++) {
            if ((hp & 1) == 0) {         // even h: cos(32 h th) = (-1)^(hp/2+1)
                float sg = ((hp >> 1) & 1) ? 1.0f : -1.0f;
                u64 ua = *(const u64*)(Ua + hp * 128 + 2 * t);
                Se = f2fma(ua, pk2(sg, sg), Se);
            } else {                     // odd h: sin(32 h th) = (-1)^((hp+1)/2)
                float sg = (((hp + 1) >> 1) & 1) ? -1.0f : 1.0f;
                u64 ub = *(const u64*)(Ub + hp * 128 + 2 * t);
                So = f2fma(ub, pk2(sg, sg), So);
            }
        }
        float a, bv;
        upk2(f2sub(Se, So), a, bv);
        *(float2*)(out + (size_t)bc * 16384 + 32 * 128 + 2 * t) =
            make_float2(a, bv);
        upk2(f2add(Se, So), a, bv);
        *(float2*)(out + (size_t)bc * 16384 + 96 * 128 + 2 * t) =
            make_float2(a, bv);
    }
}

// ===========================================================================
extern "C" void kernel_launch(void* const* d_in, const int* in_sizes, int n_in,
                              void* d_out, int out_size)
{
    const float* x     = (const float*)d_in[0];
    const float* alpha = (const float*)d_in[1];
    const float* w1r   = (const float*)d_in[2];
    const float* b1r   = (const float*)d_in[3];
    const float* w1i   = (const float*)d_in[4];
    const float* b1i   = (const float*)d_in[5];
    const float* w2r   = (const float*)d_in[6];
    const float* b2r   = (const float*)d_in[7];
    const float* w2i   = (const float*)d_in[8];
    const float* b2i   = (const float*)d_in[9];
    float* out = (float*)d_out;

    cudaFuncSetAttribute(k_fwd, cudaFuncAttributeMaxDynamicSharedMemorySize, K1_SMEM);
    cudaFuncSetAttribute(k_mlp, cudaFuncAttributeMaxDynamicSharedMemorySize, K2_SMEM);
    cudaFuncSetAttribute(k_inv, cudaFuncAttributeMaxDynamicSharedMemorySize, K3_SMEM);

    k_fwd<<<6144, 256, K1_SMEM>>>(x, alpha);
    k_mlp<<<dim3(57, 8), 256, K2_SMEM>>>(w1r, b1r, w1i, b1i, w2r, b2r, w2i, b2i);
    k_inv<<<6144, 256, K3_SMEM>>>(out);
}

// round 16
// speedup vs baseline: 1.2747x; 1.0914x over previous
#include <cuda_runtime.h>
#include <math.h>

typedef unsigned long long u64;

#define PI2_128 0.04908738521234052f   // 2*pi/128

__device__ __forceinline__ u64 pk2(float lo, float hi) {
    u64 r; asm("mov.b64 %0,{%1,%2};" : "=l"(r) : "f"(lo), "f"(hi)); return r;
}
__device__ __forceinline__ void upk2(u64 a, float& lo, float& hi) {
    asm("mov.b64 {%0,%1},%2;" : "=f"(lo), "=f"(hi) : "l"(a));
}
__device__ __forceinline__ u64 f2fma(u64 a, u64 b, u64 c) {
    u64 d; asm("fma.rn.f32x2 %0,%1,%2,%3;" : "=l"(d) : "l"(a), "l"(b), "l"(c)); return d;
}
__device__ __forceinline__ u64 f2mul(u64 a, u64 b) {
    u64 d; asm("mul.rn.f32x2 %0,%1,%2;" : "=l"(d) : "l"(a), "l"(b)); return d;
}
__device__ __forceinline__ u64 f2add(u64 a, u64 b) {
    u64 d; asm("add.rn.f32x2 %0,%1,%2;" : "=l"(d) : "l"(a), "l"(b)); return d;
}
__device__ __forceinline__ u64 f2sub(u64 a, u64 b) {
    u64 d; asm("sub.rn.f32x2 %0,%1,%2;" : "=l"(d) : "l"(a), "l"(b)); return d;
}
__device__ __forceinline__ float shrinkf(float v) {
    float a = fabsf(v) - 0.01f;
    return a > 0.f ? copysignf(a, v) : 0.f;
}

// Scratch in [bc][450] contiguous layout: element = (re,im) packed u64.
__device__ u64 g_X[6144 * 450];
__device__ u64 g_F[6144 * 450];

// ===========================================================================
// Kernel 1: forward pruned DFT, double-folded in x, folded in y.
// One CTA per (b,c).  smem 56,576 B -> 4 CTAs/SM.
// Stage 2 uses packed rotation recurrences (no scattered trig-table LDS).
// ===========================================================================
#define K1_SMEM 56576

__global__ __launch_bounds__(256, 4) void k_fwd(const float* __restrict__ x,
                                                const float* __restrict__ alpha)
{
    extern __shared__ u64 smu[];
    u64* EOe = smu;                      // [yl*33 + x], yl 0..63
    u64* EOo = smu + 2112;
    u64* Xs  = smu;                      // overlays EO after stage 1
    u64* tw  = smu + 4224;               // [x*16 + slot]
    u64* G2  = smu + 4768;               // [y*16 + slot]
    ulonglong2* cs4 = (ulonglong2*)(smu + 6816);

    const int t  = threadIdx.x;
    const int bc = blockIdx.x;
    const int b  = bc / 768, c = bc - b * 768;

    // ---- base trig table ----
    if (t < 128) {
        float cv, sv;
        sincosf(t * PI2_128, &sv, &cv);
        ulonglong2 e; e.x = pk2(cv, cv); e.y = pk2(sv, sv);
        cs4[t] = e;
    }
    __syncthreads();

    // ---- tw table: (cos(wx), -sin(wx)); slots 0..7 even w, 8..14 odd ----
    for (int i = t; i < 33 * 16; i += 256) {
        int xx = i >> 4, s = i & 15;
        if (s < 15) {
            int w = (s < 8) ? (2 * s + 2) : (2 * s - 13);
            ulonglong2 e = cs4[(w * xx) & 127];
            float cv, dum, sv;
            upk2(e.x, cv, dum);
            upk2(e.y, sv, dum);
            tw[i] = pk2(cv, -sv);
        } else {
            tw[i] = 0ull;
        }
    }

    // ---- 2 chunks of 64 rows: load + double x-fold -> EO, W-DFT -> G2 ----
    const int wrp = t >> 5, l = t & 31;
    const float* src = x + (size_t)bc * 16384;
    for (int ck = 0; ck < 2; ck++) {
        const int y0 = ck * 64;
        if (ck > 0) __syncthreads();     // EO reuse barrier
        for (int i = 0; i < 8; i++) {
            int yl = wrp * 8 + i;
            const float* row = src + (y0 + yl) * 128;
            float a = row[l];
            float u = row[32 + l];
            float m = row[64 + l];
            float q = row[96 + l];
            float Bu = __shfl_sync(0xffffffffu, u, (32 - l) & 31);
            float Dq = __shfl_sync(0xffffffffu, q, (32 - l) & 31);
            float v32 = __shfl_sync(0xffffffffu, u, 0);
            float v96 = __shfl_sync(0xffffffffu, q, 0);
            float Ep, Em, Om, Op;
            if (l == 0) {
                Ep = a + m;  Em = a - m;  Om = 0.f;  Op = 0.f;
            } else {
                float AD = a + Dq, ADm = a - Dq;
                float BC = Bu + m, CBm = m - Bu;
                Ep = AD + BC;  Em = AD - BC;
                Om = ADm + CBm; Op = ADm - CBm;
            }
            EOe[yl * 33 + l] = pk2(Ep, Om);
            EOo[yl * 33 + l] = pk2(Em, Op);
            if (l == 0) {
                u64 e32 = pk2(v32 + v96, v32 - v96);
                EOe[yl * 33 + 32] = e32;
                EOo[yl * 33 + 32] = e32;
            }
        }
        __syncthreads();

        // stage 1: thread = (2 rows, 2 slots); x loop 0..31 + x=32 tail
        {
            const int wq = t & 7;
            const int yg = t >> 3;
            const int s0 = wq * 2;
            const u64* eob = (wq < 4) ? EOe : EOo;
            u64 acc[2][2];
            acc[0][0] = 0ull; acc[0][1] = 0ull;
            acc[1][0] = 0ull; acc[1][1] = 0ull;
            for (int s = 0; s < 16; s++) {
                ulonglong2 t0 = *(const ulonglong2*)(tw + (2 * s) * 16 + s0);
                ulonglong2 t1 = *(const ulonglong2*)(tw + (2 * s + 1) * 16 + s0);
                #pragma unroll
                for (int j = 0; j < 2; j++) {
                    const u64* rp = eob + (yg + 32 * j) * 33 + 2 * s;
                    u64 e0 = rp[0], e1 = rp[1];
                    acc[j][0] = f2fma(e0, t0.x, acc[j][0]);
                    acc[j][1] = f2fma(e0, t0.y, acc[j][1]);
                    acc[j][0] = f2fma(e1, t1.x, acc[j][0]);
                    acc[j][1] = f2fma(e1, t1.y, acc[j][1]);
                }
            }
            {   // x = 32 tail
                ulonglong2 t32 = *(const ulonglong2*)(tw + 32 * 16 + s0);
                #pragma unroll
                for (int j = 0; j < 2; j++) {
                    u64 e32 = eob[(yg + 32 * j) * 33 + 32];
                    acc[j][0] = f2fma(e32, t32.x, acc[j][0]);
                    acc[j][1] = f2fma(e32, t32.y, acc[j][1]);
                }
            }
            #pragma unroll
            for (int j = 0; j < 2; j++) {
                ulonglong2 v; v.x = acc[j][0]; v.y = acc[j][1];
                *(ulonglong2*)(G2 + (y0 + yg + 32 * j) * 16 + s0) = v;
            }
        }
    }
    __syncthreads();

    // ---- in-place y-fold: rows 1..63 -> Gp; rows 65..127 -> Gm ----
    {
        u64 va[4], vb[4];
        #pragma unroll
        for (int j = 0; j < 4; j++) {
            int id = t + 256 * j;
            if (id < 1008) {
                int y = (id >> 4) + 1, s = id & 15;
                va[j] = G2[y * 16 + s];
                vb[j] = G2[(128 - y) * 16 + s];
            }
        }
        __syncthreads();
        #pragma unroll
        for (int j = 0; j < 4; j++) {
            int id = t + 256 * j;
            if (id < 1008) {
                int y = (id >> 4) + 1, s = id & 15;
                float ar, ai, br, bi;
                upk2(va[j], ar, ai); upk2(vb[j], br, bi);
                G2[y * 16 + s]        = pk2(ar + br, ai + bi);
                G2[(64 + y) * 16 + s] = pk2(ar - br, ai - bi);
            }
        }
        __syncthreads();
    }

    // ---- stage 2: C = sum Gp cos(hy), S = sum Gm sin(hy), via rotation ----
    if (t < 225) {
        const int s = t % 15, hIdx = t / 15;
        const int w = (s < 8) ? (2 * s + 2) : (2 * s - 13);
        const int wi = w - 2;
        const int h = hIdx + 2;

        // rotation constants: phi = 2h*theta
        ulonglong2 eF = cs4[(2 * h) & 127];
        u64 CF = eF.x, SF = eF.y;
        u64 NSF;
        { float sv, dum; upk2(SF, sv, dum); NSF = pk2(-sv, -sv); }
        ulonglong2 eH = cs4[h];           // cos(h th), sin(h th)
        u64 CE = pk2(1.0f, 1.0f), SE = 0ull;   // even chain: angle 2h*th*u
        u64 CO = eH.x, SO = eH.y;              // odd chain:  angle h*th*(2u+1)
        u64 C0 = 0ull, S0 = 0ull, C1 = 0ull, S1 = 0ull;

        #pragma unroll 2
        for (int u = 0; u < 32; u++) {
            u64 gpe = G2[(2 * u) * 16 + s];
            u64 gme = G2[(64 + 2 * u) * 16 + s];  // u=0 -> SE=0, harmless
            C0 = f2fma(gpe, CE, C0);
            S0 = f2fma(gme, SE, S0);
            u64 gpo = G2[(2 * u + 1) * 16 + s];
            u64 gmo = G2[(64 + 2 * u + 1) * 16 + s];
            C1 = f2fma(gpo, CO, C1);
            S1 = f2fma(gmo, SO, S1);
            // rotate both chains by phi (use OLD values on the right)
            u64 tE  = f2mul(SE, NSF);
            u64 tE2 = f2mul(CE, SF);
            CE = f2fma(CE, CF, tE);
            SE = f2fma(SE, CF, tE2);
            u64 tO  = f2mul(SO, NSF);
            u64 tO2 = f2mul(CO, SF);
            CO = f2fma(CO, CF, tO);
            SO = f2fma(SO, CF, tO2);
        }
        // y = 64 tail: cos(64 h theta) = (-1)^h
        {
            float sg = (h & 1) ? -1.0f : 1.0f;
            C0 = f2fma(G2[64 * 16 + s], pk2(sg, sg), C0);
        }

        u64 C = f2add(C0, C1), S = f2add(S0, S1);
        float Cr, Ci, Sr, Si;
        upk2(C, Cr, Ci); upk2(S, Sr, Si);
        const float sc = 1.0f / 128.0f;
        float X1r = (Cr + Si) * sc, X1i = (Ci - Sr) * sc;
        float X2r = (Cr - Si) * sc, X2i = (Ci + Sr) * sc;

        // freq embed
        float al = alpha[c];
        int cb = (c < 384) ? c : (c - 384);
        float dv = expf((float)(cb & ~1) * (-9.210340371976184f / 384.0f));
        float p1, p2;
        if (c < 384) { p1 = (float)h; p2 = (float)(128 - h); }
        else         { p1 = p2 = (float)w; }
        float e1, e2;
        if (c & 1) { e1 = cosf(p1 * dv); e2 = cosf(p2 * dv); }
        else       { e1 = sinf(p1 * dv); e2 = sinf(p2 * dv); }
        X1r += al * e1; X2r += al * e2;

        Xs[hIdx * 15 + wi]        = pk2(X1r, X1i);
        Xs[(29 - hIdx) * 15 + wi] = pk2(X2r, X2i);
    }
    __syncthreads();

    {
        u64* dst = g_X + (size_t)bc * 450;
        for (int i = t; i < 450; i += 256) dst[i] = Xs[i];
    }
}

// ===========================================================================
// Kernel 2: complex MLP per block k (96->96->96) + soft shrink.
// grid (113, 8), 1 row-tile per CTA.  Mid overlays Xt; W2 overwrites W1
// between layers.  smem 100,096 B -> 2 CTAs/SM.
// ===========================================================================
#define K2_SMEM 100096

__global__ __launch_bounds__(256) void k_mlp(
    const float* __restrict__ w1r, const float* __restrict__ b1r,
    const float* __restrict__ w1i, const float* __restrict__ b1i,
    const float* __restrict__ w2r, const float* __restrict__ b2r,
    const float* __restrict__ w2i, const float* __restrict__ b2i)
{
    extern __shared__ u64 smu[];
    u64* Xt = smu;                       // 32*97 = 3104 u64
    float* sWr = (float*)(smu + 3104);   // 9216 floats
    float* sWi = sWr + 9216;             // 9216 floats
    float* sb  = sWi + 9216;             // 384 floats

    const int t  = threadIdx.x;
    const int k  = blockIdx.y;
    const int wo = k * 9216;
    const int r0 = blockIdx.x * 32;

    if (t < 96) {
        sb[t]       = b1r[k * 96 + t];
        sb[96 + t]  = b1i[k * 96 + t];
        sb[192 + t] = b2r[k * 96 + t];
        sb[288 + t] = b2i[k * 96 + t];
    }
    for (int i = t; i < 9216; i += 256) {
        sWr[i] = w1r[wo + i];
        sWi[i] = w1i[wo + i];
    }
    for (int i = t; i < 32 * 96; i += 256) {
        int rr = i & 31, ci = i >> 5;
        int R = r0 + rr; if (R > 3599) R = 3599;
        int bb = R / 450, m = R - bb * 450;
        Xt[rr * 97 + ci] = g_X[((size_t)(bb * 768 + k * 96 + ci)) * 450 + m];
    }
    __syncthreads();

    const int r  = t & 31;
    const int cg = t >> 5;
    const int c0 = cg * 12;
    u64 ar[6], ai[6];

    // ---- layer 1 ----
    #pragma unroll
    for (int p = 0; p < 6; p++) {
        int cc = c0 + 2 * p;
        float br0 = sb[cc], bi0 = sb[96 + cc];
        float br1 = sb[cc + 1], bi1 = sb[96 + cc + 1];
        ar[p] = pk2(br0 - bi0, br1 - bi1);
        ai[p] = pk2(br0 + bi0, br1 + bi1);
    }
    {
        const u64* xrow = Xt + r * 97;
        #pragma unroll 4
        for (int i = 0; i < 96; i++) {
            float xr, xi; upk2(xrow[i], xr, xi);
            u64 xrr = pk2(xr, xr), xii = pk2(xi, xi), xin = pk2(-xi, -xi);
            const float* wr  = sWr + i * 96 + c0;
            const float* wii = sWi + i * 96 + c0;
            ulonglong2 wrq0 = *(const ulonglong2*)(wr);
            ulonglong2 wrq1 = *(const ulonglong2*)(wr + 4);
            ulonglong2 wrq2 = *(const ulonglong2*)(wr + 8);
            ulonglong2 wiq0 = *(const ulonglong2*)(wii);
            ulonglong2 wiq1 = *(const ulonglong2*)(wii + 4);
            ulonglong2 wiq2 = *(const ulonglong2*)(wii + 8);
            u64 wrA[6] = {wrq0.x, wrq0.y, wrq1.x, wrq1.y, wrq2.x, wrq2.y};
            u64 wiA[6] = {wiq0.x, wiq0.y, wiq1.x, wiq1.y, wiq2.x, wiq2.y};
            #pragma unroll
            for (int p = 0; p < 6; p++) {
                ar[p] = f2fma(xrr, wrA[p], ar[p]);
                ar[p] = f2fma(xin, wiA[p], ar[p]);
                ai[p] = f2fma(xii, wrA[p], ai[p]);
                ai[p] = f2fma(xrr, wiA[p], ai[p]);
            }
        }
    }
    __syncthreads();   // all layer-1 reads of Xt and W1 complete

    // ---- write mid into Xt (overlay) + load W2 over W1 ----
    #pragma unroll
    for (int p = 0; p < 6; p++) {
        float r1a, r1b, i1a, i1b;
        upk2(ar[p], r1a, r1b); upk2(ai[p], i1a, i1b);
        Xt[r * 97 + c0 + 2 * p]     = pk2(r1a, i1a);
        Xt[r * 97 + c0 + 2 * p + 1] = pk2(r1b, i1b);
    }
    for (int i = t; i < 9216; i += 256) {
        sWr[i] = w2r[wo + i];
        sWi[i] = w2i[wo + i];
    }
    __syncthreads();

    // ---- layer 2 ----
    #pragma unroll
    for (int p = 0; p < 6; p++) {
        int cc = c0 + 2 * p;
        float br0 = sb[192 + cc], bi0 = sb[288 + cc];
        float br1 = sb[192 + cc + 1], bi1 = sb[288 + cc + 1];
        ar[p] = pk2(br0 - bi0, br1 - bi1);
        ai[p] = pk2(br0 + bi0, br1 + bi1);
    }
    {
        const u64* mrow = Xt + r * 97;
        #pragma unroll 4
        for (int i = 0; i < 96; i++) {
            float xr, xi; upk2(mrow[i], xr, xi);
            u64 xrr = pk2(xr, xr), xii = pk2(xi, xi), xin = pk2(-xi, -xi);
            const float* wr  = sWr + i * 96 + c0;
            const float* wii = sWi + i * 96 + c0;
            ulonglong2 wrq0 = *(const ulonglong2*)(wr);
            ulonglong2 wrq1 = *(const ulonglong2*)(wr + 4);
            ulonglong2 wrq2 = *(const ulonglong2*)(wr + 8);
            ulonglong2 wiq0 = *(const ulonglong2*)(wii);
            ulonglong2 wiq1 = *(const ulonglong2*)(wii + 4);
            ulonglong2 wiq2 = *(const ulonglong2*)(wii + 8);
            u64 wrA[6] = {wrq0.x, wrq0.y, wrq1.x, wrq1.y, wrq2.x, wrq2.y};
            u64 wiA[6] = {wiq0.x, wiq0.y, wiq1.x, wiq1.y, wiq2.x, wiq2.y};
            #pragma unroll
            for (int p = 0; p < 6; p++) {
                ar[p] = f2fma(xrr, wrA[p], ar[p]);
                ar[p] = f2fma(xin, wiA[p], ar[p]);
                ai[p] = f2fma(xii, wrA[p], ai[p]);
                ai[p] = f2fma(xrr, wiA[p], ai[p]);
            }
        }
    }
    __syncthreads();   // all layer-2 reads of Xt complete

    // ---- shrink -> Xt, then coalesced store ----
    #pragma unroll
    for (int p = 0; p < 6; p++) {
        float ra, rb, ia, ib;
        upk2(ar[p], ra, rb); upk2(ai[p], ia, ib);
        Xt[r * 97 + c0 + 2 * p]     = pk2(shrinkf(ra), shrinkf(ia));
        Xt[r * 97 + c0 + 2 * p + 1] = pk2(shrinkf(rb), shrinkf(ib));
    }
    __syncthreads();

    for (int i = t; i < 32 * 96; i += 256) {
        int rr = i & 31, ci = i >> 5;
        int R = r0 + rr;
        if (R < 3600) {
            int bb = R / 450, m = R - bb * 450;
            g_F[((size_t)(bb * 768 + k * 96 + ci)) * 450 + m] = Xt[rr * 97 + ci];
        }
    }
}

// ===========================================================================
// Kernel 3: sparse inverse DFT, x-folded + double y-folded (h-parity).
// 2 CTAs/SM, p-inner float4 quads.  (unchanged from R14, 513-us config)
// ===========================================================================
#define K3_SMEM 52688

__global__ __launch_bounds__(256, 2) void k_inv(float* __restrict__ out)
{
    extern __shared__ u64 smu[];
    u64* Fp = smu;                       // 450
    ulonglong2* cs4 = (ulonglong2*)(smu + 450);
    u64* Pc = smu + 706;                 // [hi*66 + x]
    u64* Ps = smu + 2686;
    float* Ua = (float*)(smu + 4666);    // [hp*128 + x], pre-scaled by 1/64
    float* Ub = (float*)(smu + 5626);

    const int t  = threadIdx.x;
    const int bc = blockIdx.x;

    if (t < 128) {
        float cv, sv;
        sincosf(t * PI2_128, &sv, &cv);
        ulonglong2 e; e.x = pk2(cv, cv); e.y = pk2(sv, sv);
        cs4[t] = e;
    }
    {
        const u64* srcF = g_F + (size_t)bc * 450;
        for (int i = t; i < 450; i += 256) Fp[i] = srcF[i];
    }
    __syncthreads();

    // ---- stage 1: Pc/Ps[hi][x] = Sum_w F * (cos, sin)((w+2) x), x=0..64 ----
    if (t < 240) {
        const int hi = t % 30, xg = t / 30;
        u64 F[15];
        #pragma unroll
        for (int w = 0; w < 15; w++) F[w] = Fp[hi * 15 + w];
        for (int q = 0; q < 9; q++) {
            int xx = xg + 8 * q;
            if (xx > 64) break;
            const int stp = (2 * xx) & 127;
            u64 cA = 0ull, sA = 0ull, cB = 0ull, sB = 0ull;
            int iA = stp;
            int iB = (3 * xx) & 127;
            #pragma unroll
            for (int w = 0; w < 15; w += 2) {
                ulonglong2 tb = cs4[iA];
                cA = f2fma(F[w], tb.x, cA);
                sA = f2fma(F[w], tb.y, sA);
                iA = (iA + stp) & 127;
            }
            #pragma unroll
            for (int w = 1; w < 15; w += 2) {
                ulonglong2 tb = cs4[iB];
                cB = f2fma(F[w], tb.x, cB);
                sB = f2fma(F[w], tb.y, sB);
                iB = (iB + stp) & 127;
            }
            Pc[hi * 66 + xx] = f2add(cA, cB);
            Ps[hi * 66 + xx] = f2add(sA, sB);
        }
    }
    __syncthreads();

    // ---- combine: fold h-pairs + reconstruct x and 128-x (scaled 1/64) ----
    for (int idx = t; idx < 15 * 65; idx += 256) {
        int hp = idx / 65, xx = idx - hp * 65;
        const float sc = 1.0f / 64.0f;
        float c1r, c1i, s1r, s1i, c2r, c2i, s2r, s2i;
        upk2(Pc[hp * 66 + xx], c1r, c1i);
        upk2(Ps[hp * 66 + xx], s1r, s1i);
        upk2(Pc[(29 - hp) * 66 + xx], c2r, c2i);
        upk2(Ps[(29 - hp) * 66 + xx], s2r, s2i);
        float p1re = c1r - s1i, p1im = c1i + s1r;
        float p2re = c2r - s2i, p2im = c2i + s2r;
        Ua[hp * 128 + xx] = (p1re + p2re) * sc;
        Ub[hp * 128 + xx] = (p1im - p2im) * sc;
        if (xx >= 1 && xx <= 63) {
            float m1re = c1r + s1i, m1im = c1i - s1r;
            float m2re = c2r + s2i, m2im = c2i - s2r;
            Ua[hp * 128 + 128 - xx] = (m1re + m2re) * sc;
            Ub[hp * 128 + 128 - xx] = (m1im - m2im) * sc;
        }
    }
    __syncthreads();

    // ---- stage 2: h-parity split, float4 x-quads -> 4 output rows per y ----
    {
        const int xg = t & 15;            // quads: x = 4*xg + 64*p, p=0,1
        const int yg = t >> 4;            // y in {yg, yg+16}
        ulonglong2 Ae[2][2], Ao[2][2], Be[2][2], Bo[2][2];
        #pragma unroll
        for (int yi = 0; yi < 2; yi++)
            #pragma unroll
            for (int p = 0; p < 2; p++) {
                Ae[yi][p].x = 0ull; Ae[yi][p].y = 0ull;
                Ao[yi][p].x = 0ull; Ao[yi][p].y = 0ull;
                Be[yi][p].x = 0ull; Be[yi][p].y = 0ull;
                Bo[yi][p].x = 0ull; Bo[yi][p].y = 0ull;
            }

        #pragma unroll
        for (int hp = 0; hp < 15; hp += 2) {      // even h = hp+2
            const int h = hp + 2;
            ulonglong2 ua[2], ub[2];
            #pragma unroll
            for (int p = 0; p < 2; p++) {
                ua[p] = *(const ulonglong2*)(Ua + hp * 128 + 4 * xg + 64 * p);
                ub[p] = *(const ulonglong2*)(Ub + hp * 128 + 4 * xg + 64 * p);
            }
            #pragma unroll
            for (int yi = 0; yi < 2; yi++) {
                ulonglong2 tb = cs4[(h * (yg + 16 * yi)) & 127];
                #pragma unroll
                for (int p = 0; p < 2; p++) {
                    Ae[yi][p].x = f2fma(ua[p].x, tb.x, Ae[yi][p].x);
                    Ae[yi][p].y = f2fma(ua[p].y, tb.x, Ae[yi][p].y);
                    Be[yi][p].x = f2fma(ub[p].x, tb.y, Be[yi][p].x);
                    Be[yi][p].y = f2fma(ub[p].y, tb.y, Be[yi][p].y);
                }
            }
        }
        #pragma unroll
        for (int hp = 1; hp < 15; hp += 2) {      // odd h
            const int h = hp + 2;
            ulonglong2 ua[2], ub[2];
            #pragma unroll
            for (int p = 0; p < 2; p++) {
                ua[p] = *(const ulonglong2*)(Ua + hp * 128 + 4 * xg + 64 * p);
                ub[p] = *(const ulonglong2*)(Ub + hp * 128 + 4 * xg + 64 * p);
            }
            #pragma unroll
            for (int yi = 0; yi < 2; yi++) {
                ulonglong2 tb = cs4[(h * (yg + 16 * yi)) & 127];
                #pragma unroll
                for (int p = 0; p < 2; p++) {
                    Ao[yi][p].x = f2fma(ua[p].x, tb.x, Ao[yi][p].x);
                    Ao[yi][p].y = f2fma(ua[p].y, tb.x, Ao[yi][p].y);
                    Bo[yi][p].x = f2fma(ub[p].x, tb.y, Bo[yi][p].x);
                    Bo[yi][p].y = f2fma(ub[p].y, tb.y, Bo[yi][p].y);
                }
            }
        }

        float* outp = out + (size_t)bc * 16384 + 4 * xg;
        #pragma unroll
        for (int yi = 0; yi < 2; yi++) {
            int y = yg + 16 * yi;
            #pragma unroll
            for (int p = 0; p < 2; p++) {
                u64 Px = f2add(Ae[yi][p].x, Ao[yi][p].x);
                u64 Py = f2add(Ae[yi][p].y, Ao[yi][p].y);
                u64 Qx = f2sub(Ae[yi][p].x, Ao[yi][p].x);
                u64 Qy = f2sub(Ae[yi][p].y, Ao[yi][p].y);
                u64 Rx = f2add(Be[yi][p].x, Bo[yi][p].x);
                u64 Ry = f2add(Be[yi][p].y, Bo[yi][p].y);
                u64 Sx = f2sub(Be[yi][p].x, Bo[yi][p].x);
                u64 Sy = f2sub(Be[yi][p].y, Bo[yi][p].y);
                float a0, a1, a2, a3;
                // out[y] = P - R
                upk2(f2sub(Px, Rx), a0, a1); upk2(f2sub(Py, Ry), a2, a3);
                *(float4*)(outp + y * 128 + 64 * p) = make_float4(a0, a1, a2, a3);
                // out[64-y] = Q + S
                upk2(f2add(Qx, Sx), a0, a1); upk2(f2add(Qy, Sy), a2, a3);
                *(float4*)(outp + (64 - y) * 128 + 64 * p) = make_float4(a0, a1, a2, a3);
                if (y > 0) {
                    // out[64+y] = Q - S
                    upk2(f2sub(Qx, Sx), a0, a1); upk2(f2sub(Qy, Sy), a2, a3);
                    *(float4*)(outp + (64 + y) * 128 + 64 * p) = make_float4(a0, a1, a2, a3);
                    // out[128-y] = P + R
                    upk2(f2add(Px, Rx), a0, a1); upk2(f2add(Py, Ry), a2, a3);
                    *(float4*)(outp + (128 - y) * 128 + 64 * p) = make_float4(a0, a1, a2, a3);
                }
            }
        }
    }

    // ---- rows y = 32 and y = 96 ----
    if (t < 64) {
        u64 Se = 0ull, So = 0ull;
        #pragma unroll
        for (int hp = 0; hp < 15; hp++) {
            if ((hp & 1) == 0) {         // even h: cos(32 h th) = (-1)^(hp/2+1)
                float sg = ((hp >> 1) & 1) ? 1.0f : -1.0f;
                u64 ua = *(const u64*)(Ua + hp * 128 + 2 * t);
                Se = f2fma(ua, pk2(sg, sg), Se);
            } else {                     // odd h: sin(32 h th) = (-1)^((hp+1)/2)
                float sg = (((hp + 1) >> 1) & 1) ? -1.0f : 1.0f;
                u64 ub = *(const u64*)(Ub + hp * 128 + 2 * t);
                So = f2fma(ub, pk2(sg, sg), So);
            }
        }
        float a, bv;
        upk2(f2sub(Se, So), a, bv);
        *(float2*)(out + (size_t)bc * 16384 + 32 * 128 + 2 * t) =
            make_float2(a, bv);
        upk2(f2add(Se, So), a, bv);
        *(float2*)(out + (size_t)bc * 16384 + 96 * 128 + 2 * t) =
            make_float2(a, bv);
    }
}

// ===========================================================================
extern "C" void kernel_launch(void* const* d_in, const int* in_sizes, int n_in,
                              void* d_out, int out_size)
{
    const float* x     = (const float*)d_in[0];
    const float* alpha = (const float*)d_in[1];
    const float* w1r   = (const float*)d_in[2];
    const float* b1r   = (const float*)d_in[3];
    const float* w1i   = (const float*)d_in[4];
    const float* b1i   = (const float*)d_in[5];
    const float* w2r   = (const float*)d_in[6];
    const float* b2r   = (const float*)d_in[7];
    const float* w2i   = (const float*)d_in[8];
    const float* b2i   = (const float*)d_in[9];
    float* out = (float*)d_out;

    cudaFuncSetAttribute(k_fwd, cudaFuncAttributeMaxDynamicSharedMemorySize, K1_SMEM);
    cudaFuncSetAttribute(k_mlp, cudaFuncAttributeMaxDynamicSharedMemorySize, K2_SMEM);
    cudaFuncSetAttribute(k_inv, cudaFuncAttributeMaxDynamicSharedMemorySize, K3_SMEM);

    k_fwd<<<6144, 256, K1_SMEM>>>(x, alpha);
    k_mlp<<<dim3(113, 8), 256, K2_SMEM>>>(w1r, b1r, w1i, b1i, w2r, b2r, w2i, b2i);
    k_inv<<<6144, 256, K3_SMEM>>>(out);
}